// round 6
// baseline (speedup 1.0000x reference)
#include <cuda_runtime.h>
#include <cuda_bf16.h>

#define BB 256
#define TT 512
#define LL 64

__device__ __forceinline__ void fma2(unsigned long long& d,
                                     unsigned long long a,
                                     unsigned long long b) {
    asm("fma.rn.f32x2 %0, %1, %2, %0;" : "+l"(d) : "l"(a), "l"(b));
}
__device__ __forceinline__ unsigned long long add2(unsigned long long a,
                                                   unsigned long long b) {
    unsigned long long r;
    asm("add.rn.f32x2 %0, %1, %2;" : "=l"(r) : "l"(a), "l"(b));
    return r;
}
__device__ __forceinline__ unsigned long long pack2(float lo, float hi) {
    unsigned long long r;
    asm("mov.b64 %0, {%1, %2};" : "=l"(r) : "f"(lo), "f"(hi));
    return r;
}
__device__ __forceinline__ float2 unpack2(unsigned long long v) {
    float2 r;
    asm("mov.b64 {%0, %1}, %2;" : "=f"(r.x), "=f"(r.y) : "l"(v));
    return r;
}

// One CTA per batch element, 128 threads. Pair layout: j = tid>>1 (output
// label), ih = tid&1 (i-half). Each thread accumulates half of the i-sum
// (16 FFMA2), pair-combined with one shfl_xor(1). Renorm every 4 steps by
// v[0] (exact; folded into S). Ballots (even lanes only) logged to SMEM;
// labels + transition score computed in parallel post-loop.
__global__ __launch_bounds__(128, 2)
void crf_fwd_kernel(const float* __restrict__ y_true,
                    const float* __restrict__ y_pred,
                    const float* __restrict__ trans,
                    float* __restrict__ out)
{
    __shared__ float trans_sh[LL * LL];              // 16KB raw trans
    __shared__ __align__(16) float vsh[2][LL];       // double-buffered state
    __shared__ unsigned bal_sh[TT][4];               // 8KB one-hot ballots (4 warps)
    __shared__ int lab_sh[TT];                       // 2KB decoded labels
    __shared__ float red_sh[3][4];                   // final reductions

    const int tid  = threadIdx.x;
    const int lane = tid & 31;
    const int w    = tid >> 5;
    const int j    = tid >> 1;     // output label
    const int ih   = tid & 1;      // which half of the i-sum
    const int b    = blockIdx.x;

    const float* yp = y_pred + (size_t)b * TT * LL;
    const float* yt = y_true + (size_t)b * TT * LL;

    #pragma unroll
    for (int k = 0; k < (LL * LL) / 128; ++k)
        trans_sh[k * 128 + tid] = trans[k * 128 + tid];
    __syncthreads();

    // E half-column for label j, i in [ih*32, ih*32+32), packed in i-pairs
    unsigned long long Epk[16];
    #pragma unroll
    for (int k = 0; k < 16; ++k) {
        float t0 = __expf(trans_sh[(ih * 32 + 2 * k    ) * LL + j]);
        float t1 = __expf(trans_sh[(ih * 32 + 2 * k + 1) * LL + j]);
        Epk[k] = pack2(t0, t1);
    }

    // ---- t = 0 ----
    float e0 = yp[j];
    float y0 = yt[j];
    float pt = e0 * y0;             // duplicated across pair; halved at the end
    float nv = __expf(e0);
    {
        unsigned bal = __ballot_sync(0xffffffffu, (y0 > 0.5f) && (ih == 0));
        if (lane == 0) bal_sh[0][w] = bal;
    }
    if (ih == 0) vsh[0][j] = nv;
    __syncthreads();

    float S = 0.0f;   // accumulated log-scale (identical across threads)

    // Distance-4 emission prefetch ring
    float eb[4], yb[4];
    #pragma unroll
    for (int t = 1; t <= 4; ++t) {
        eb[t & 3] = yp[t * LL + j];
        yb[t & 3] = yt[t * LL + j];
    }

    #pragma unroll 4
    for (int t = 1; t < TT; ++t) {
        const int p = t & 1;
        const int q = p ^ 1;

        float e  = eb[t & 3];
        float yv = yb[t & 3];
        int tn = (t + 4 < TT) ? (t + 4) : t;    // clamped; dead slot never consumed
        eb[t & 3] = yp[tn * LL + j];
        yb[t & 3] = yt[tn * LL + j];

        // Latency producers hoisted ahead of the matvec
        float g = __expf(e);
        if ((t & 3) == 0) {
            float scale = vsh[q][0];            // broadcast LDS; exact via S
            S += __logf(scale);
            g *= __fdividef(1.0f, scale);
        }
        pt = fmaf(e, yv, pt);
        unsigned bal = __ballot_sync(0xffffffffu, (yv > 0.5f) && (ih == 0));
        if (lane == 0) bal_sh[t][w] = bal;

        // Half matvec: partial_j = sum_{i in my half} v[i] * E[i][j]
        // 16 FFMA2 in 4 chains (depth 4)
        const ulonglong2* vp =
            reinterpret_cast<const ulonglong2*>(vsh[q] + ih * 32);
        unsigned long long a0 = 0ull, a1 = 0ull, a2 = 0ull, a3 = 0ull;
        #pragma unroll
        for (int i = 0; i < 2; ++i) {
            ulonglong2 va = vp[4 * i + 0];
            ulonglong2 vb = vp[4 * i + 1];
            ulonglong2 vc = vp[4 * i + 2];
            ulonglong2 vd = vp[4 * i + 3];
            fma2(a0, va.x, Epk[8 * i + 0]);
            fma2(a1, va.y, Epk[8 * i + 1]);
            fma2(a2, vb.x, Epk[8 * i + 2]);
            fma2(a3, vb.y, Epk[8 * i + 3]);
            fma2(a0, vc.x, Epk[8 * i + 4]);
            fma2(a1, vc.y, Epk[8 * i + 5]);
            fma2(a2, vd.x, Epk[8 * i + 6]);
            fma2(a3, vd.y, Epk[8 * i + 7]);
        }
        float2 fs = unpack2(add2(add2(a0, a1), add2(a2, a3)));
        float part = fs.x + fs.y;
        part += __shfl_xor_sync(0xffffffffu, part, 1);   // pair combine
        nv = part * g;

        if (ih == 0) vsh[p][j] = nv;
        __syncthreads();
    }

    // ---- Parallel label decode + transition score (post-loop) ----
    for (int t = tid; t < TT; t += 128) {
        unsigned b0 = bal_sh[t][0], b1 = bal_sh[t][1];
        unsigned b2 = bal_sh[t][2], b3 = bal_sh[t][3];
        int lab;
        if      (b0) lab =      ((__ffs(b0) - 1) >> 1);
        else if (b1) lab = 16 + ((__ffs(b1) - 1) >> 1);
        else if (b2) lab = 32 + ((__ffs(b2) - 1) >> 1);
        else         lab = 48 + ((__ffs(b3) - 1) >> 1);
        lab_sh[t] = lab;
    }
    __syncthreads();

    float tsc = 0.0f;
    for (int t = tid; t < TT - 1; t += 128)
        tsc += trans_sh[lab_sh[t] * LL + lab_sh[t + 1]];

    // ---- Final reductions (nv/pt duplicated per pair -> halve) ----
    float s = nv;
    #pragma unroll
    for (int o = 16; o; o >>= 1) s   += __shfl_xor_sync(0xffffffffu, s, o);
    #pragma unroll
    for (int o = 16; o; o >>= 1) pt  += __shfl_xor_sync(0xffffffffu, pt, o);
    #pragma unroll
    for (int o = 16; o; o >>= 1) tsc += __shfl_xor_sync(0xffffffffu, tsc, o);
    if (lane == 0) { red_sh[0][w] = s; red_sh[1][w] = pt; red_sh[2][w] = tsc; }
    __syncthreads();

    if (tid == 0) {
        float tot   = 0.5f * (red_sh[0][0] + red_sh[0][1] + red_sh[0][2] + red_sh[0][3]);
        float point = 0.5f * (red_sh[1][0] + red_sh[1][1] + red_sh[1][2] + red_sh[1][3]);
        float trsc  =        (red_sh[2][0] + red_sh[2][1] + red_sh[2][2] + red_sh[2][3]);
        float log_norm = __logf(tot) + S;
        out[b] = -(point + trsc - log_norm);
    }
}

extern "C" void kernel_launch(void* const* d_in, const int* in_sizes, int n_in,
                              void* d_out, int out_size)
{
    const float* y_true = (const float*)d_in[0];
    const float* y_pred = (const float*)d_in[1];
    const float* trans  = (const float*)d_in[2];
    float* out = (float*)d_out;
    crf_fwd_kernel<<<BB, 128>>>(y_true, y_pred, trans, out);
}

// round 10
// speedup vs baseline: 1.8963x; 1.8963x over previous
#include <cuda_runtime.h>
#include <cuda_bf16.h>

#define BB 256
#define TT 512
#define LL 64

typedef unsigned long long ull;

__device__ __forceinline__ void fma2(ull& d, ull a, ull b) {
    asm("fma.rn.f32x2 %0, %1, %2, %0;" : "+l"(d) : "l"(a), "l"(b));
}
__device__ __forceinline__ ull add2(ull a, ull b) {
    ull r;
    asm("add.rn.f32x2 %0, %1, %2;" : "=l"(r) : "l"(a), "l"(b));
    return r;
}
__device__ __forceinline__ ull pack2(float lo, float hi) {
    ull r;
    asm("mov.b64 %0, {%1, %2};" : "=l"(r) : "f"(lo), "f"(hi));
    return r;
}
__device__ __forceinline__ float2 unpack2(ull v) {
    float2 r;
    asm("mov.b64 {%0, %1}, %2;" : "=f"(r.x), "=f"(r.y) : "l"(v));
    return r;
}

// One CTA per batch element, 64 threads = one per label j (R5 shape).
// Barrier-split matvec: own-half partial (i in own warp's range) computed
// PRE-barrier from own warp's just-written SMEM half; only the other half's
// partial sits on the post-barrier critical path. Renorm every 4 steps by
// v[0] read post-barrier (exact; folded into S).
__global__ __launch_bounds__(64, 2)
void crf_fwd_kernel(const float* __restrict__ y_true,
                    const float* __restrict__ y_pred,
                    const float* __restrict__ trans,
                    float* __restrict__ out)
{
    __shared__ float trans_sh[LL * LL];              // 16KB raw trans
    __shared__ __align__(16) float vsh[2][LL];       // double-buffered state
    __shared__ unsigned bal_sh[TT][2];               // 4KB one-hot ballots
    __shared__ int lab_sh[TT];                       // 2KB decoded labels
    __shared__ float red_sh[3][2];                   // final reductions

    const int tid  = threadIdx.x;
    const int lane = tid & 31;
    const int w    = tid >> 5;
    const int b    = blockIdx.x;

    const float* yp = y_pred + (size_t)b * TT * LL;
    const float* yt = y_true + (size_t)b * TT * LL;

    #pragma unroll
    for (int k = 0; k < (LL * LL) / 64; ++k)
        trans_sh[k * 64 + tid] = trans[k * 64 + tid];
    __syncthreads();

    // E column for label j=tid, packed in i-pairs: Epk[k] covers i=2k,2k+1
    ull Epk[LL / 2];
    #pragma unroll
    for (int k = 0; k < LL / 2; ++k) {
        float t0 = __expf(trans_sh[(2 * k    ) * LL + tid]);
        float t1 = __expf(trans_sh[(2 * k + 1) * LL + tid]);
        Epk[k] = pack2(t0, t1);
    }

    // ---- t = 0 ----
    float e0 = yp[tid];
    float y0 = yt[tid];
    float pt = e0 * y0;             // point-score accumulator
    float nv = __expf(e0);          // u_0[j]
    {
        unsigned bal = __ballot_sync(0xffffffffu, y0 > 0.5f);
        if (lane == 0) bal_sh[0][w] = bal;
    }
    vsh[0][tid] = nv;
    __syncthreads();

    float S = 0.0f;   // accumulated log-scale (identical across threads)

    // Distance-4 emission prefetch ring (same shape as the 74us build)
    float eb[4], yb[4];
    #pragma unroll
    for (int t = 1; t <= 4; ++t) {
        eb[t & 3] = yp[t * LL + tid];
        yb[t & 3] = yt[t * LL + tid];
    }

    const int ow = w << 5;          // own i-range base   (w*32)
    const int xw = (w ^ 1) << 5;    // other i-range base

    #pragma unroll 4
    for (int t = 1; t < TT; ++t) {
        const int p = t & 1;
        const int q = p ^ 1;

        float e  = eb[t & 3];
        float yv = yb[t & 3];
        int tn = (t + 4 < TT) ? (t + 4) : t;    // clamped; dead slot never consumed
        eb[t & 3] = yp[tn * LL + tid];
        yb[t & 3] = yt[tn * LL + tid];

        // Independent latency producers
        float g = __expf(e);
        pt = fmaf(e, yv, pt);
        unsigned bal = __ballot_sync(0xffffffffu, yv > 0.5f);
        if (lane == 0) bal_sh[t][w] = bal;

        // --- PRE-barrier: own-half partial (own warp wrote this half,
        //     made lane-visible by the __syncwarp at end of prev iter) ---
        const ulonglong2* vo = reinterpret_cast<const ulonglong2*>(vsh[q] + ow);
        ull a0 = 0ull, a1 = 0ull, a2 = 0ull, a3 = 0ull;
        #pragma unroll
        for (int i = 0; i < 2; ++i) {
            ulonglong2 va = vo[4 * i + 0];
            ulonglong2 vb = vo[4 * i + 1];
            ulonglong2 vc = vo[4 * i + 2];
            ulonglong2 vd = vo[4 * i + 3];
            const int kb = (ow >> 1) + 8 * i;
            fma2(a0, va.x, Epk[kb + 0]);
            fma2(a1, va.y, Epk[kb + 1]);
            fma2(a2, vb.x, Epk[kb + 2]);
            fma2(a3, vb.y, Epk[kb + 3]);
            fma2(a0, vc.x, Epk[kb + 4]);
            fma2(a1, vc.y, Epk[kb + 5]);
            fma2(a2, vd.x, Epk[kb + 6]);
            fma2(a3, vd.y, Epk[kb + 7]);
        }
        ull sa = add2(add2(a0, a1), add2(a2, a3));

        __syncthreads();

        // Renorm scale must be read post-barrier (element 0 is warp 0's data)
        float scale = 1.0f;
        if ((t & 3) == 0) scale = vsh[q][0];

        // --- POST-barrier: other-half partial ---
        const ulonglong2* vx = reinterpret_cast<const ulonglong2*>(vsh[q] + xw);
        ull b0 = 0ull, b1 = 0ull, b2 = 0ull, b3 = 0ull;
        #pragma unroll
        for (int i = 0; i < 2; ++i) {
            ulonglong2 va = vx[4 * i + 0];
            ulonglong2 vb = vx[4 * i + 1];
            ulonglong2 vc = vx[4 * i + 2];
            ulonglong2 vd = vx[4 * i + 3];
            const int kb = (xw >> 1) + 8 * i;
            fma2(b0, va.x, Epk[kb + 0]);
            fma2(b1, va.y, Epk[kb + 1]);
            fma2(b2, vb.x, Epk[kb + 2]);
            fma2(b3, vb.y, Epk[kb + 3]);
            fma2(b0, vc.x, Epk[kb + 4]);
            fma2(b1, vc.y, Epk[kb + 5]);
            fma2(b2, vd.x, Epk[kb + 6]);
            fma2(b3, vd.y, Epk[kb + 7]);
        }
        ull sb = add2(add2(b0, b1), add2(b2, b3));
        float2 fs = unpack2(add2(sa, sb));
        float acc = fs.x + fs.y;

        if ((t & 3) == 0) {
            S += __logf(scale);                 // exact: folded back via S
            g *= __fdividef(1.0f, scale);
        }
        nv = acc * g;

        vsh[p][tid] = nv;
        __syncwarp();                           // own half visible to own lanes
    }

    // ---- Parallel label decode + transition score (post-loop) ----
    __syncthreads();
    #pragma unroll
    for (int t = tid; t < TT; t += 64) {
        unsigned b0 = bal_sh[t][0], b1 = bal_sh[t][1];
        lab_sh[t] = b0 ? (__ffs(b0) - 1) : (32 + __ffs(b1) - 1);
    }
    __syncthreads();

    float tsc = 0.0f;
    #pragma unroll
    for (int t = tid; t < TT - 1; t += 64)
        tsc += trans_sh[lab_sh[t] * LL + lab_sh[t + 1]];

    // ---- Final reductions: sum(v_last), point score, trans score ----
    float s = nv;
    #pragma unroll
    for (int o = 16; o; o >>= 1) s   += __shfl_xor_sync(0xffffffffu, s, o);
    #pragma unroll
    for (int o = 16; o; o >>= 1) pt  += __shfl_xor_sync(0xffffffffu, pt, o);
    #pragma unroll
    for (int o = 16; o; o >>= 1) tsc += __shfl_xor_sync(0xffffffffu, tsc, o);
    if (lane == 0) { red_sh[0][w] = s; red_sh[1][w] = pt; red_sh[2][w] = tsc; }
    __syncthreads();

    if (tid == 0) {
        float tot      = red_sh[0][0] + red_sh[0][1];
        float point    = red_sh[1][0] + red_sh[1][1];
        float transsc  = red_sh[2][0] + red_sh[2][1];
        float log_norm = __logf(tot) + S;
        out[b] = -(point + transsc - log_norm);
    }
}

extern "C" void kernel_launch(void* const* d_in, const int* in_sizes, int n_in,
                              void* d_out, int out_size)
{
    const float* y_true = (const float*)d_in[0];
    const float* y_pred = (const float*)d_in[1];
    const float* trans  = (const float*)d_in[2];
    float* out = (float*)d_out;
    crf_fwd_kernel<<<BB, 64>>>(y_true, y_pred, trans, out);
}